// round 11
// baseline (speedup 1.0000x reference)
#include <cuda_runtime.h>
#include <cuda_bf16.h>
#include <stdint.h>

#define N_ENTS 50000
#define N_RELS 500
#define N_TOT  50500
#define EMB    256
#define N_EDGES 400000
#define BATCH  512
#define BN_EPS 1e-5f
#define KS2    512   // h|l storage width (bf16x3 streams 768 via chunk tables)

// ---------------- scratch (__device__ globals, no allocations) ----------------
__device__ float g_XR[(size_t)N_TOT * EMB];
__device__ float g_agg[(size_t)N_TOT * EMB];        // XR-branch segsum, then GEMM output
__device__ float g_aggX[(size_t)N_ENTS * EMB];      // X-branch segsum, then GEMM output
__device__ float g_hr[(size_t)BATCH * EMB];
__device__ float g_csum[2 * EMB];
__device__ float g_csq[2 * EMB];
__device__ float g_scale[2 * EMB];
__device__ float g_shift[2 * EMB];

// h|l split buffers: [n, 512] bf16, cols 0-255 = hi, 256-511 = lo
__device__ __nv_bfloat16 g_SA1[(size_t)N_TOT * KS2];     // split of XR (score B-side)
__device__ __nv_bfloat16 g_SA2[(size_t)N_TOT * KS2];     // split of aggR, then of XRrf
__device__ __nv_bfloat16 g_SA3[(size_t)N_ENTS * KS2];    // split of aggX, then of Xef
__device__ __nv_bfloat16 g_WbC[512 * KS2];               // gcn weights: rows 0-255 g2, 256-511 g1
__device__ __nv_bfloat16 g_Wb[EMB * KS2];                // lin weights H1
__device__ __nv_bfloat16 g_Wb2[EMB * KS2];               // lin weights H2
__device__ __nv_bfloat16 g_hrA[(size_t)BATCH * KS2];     // split hr

// quaternion block tables
__constant__ int   c_comp[4][4] = {{0,1,2,3},{1,0,3,2},{2,3,0,1},{3,2,1,0}};
__constant__ float c_sign[4][4] = {{ 1.f, 1.f, 1.f, 1.f},
                                   {-1.f, 1.f, 1.f,-1.f},
                                   {-1.f,-1.f, 1.f, 1.f},
                                   {-1.f, 1.f,-1.f, 1.f}};

// bf16x3 chunk schedule (64-half chunks): AhBh x4, AlBh x4, AhBl x4
__constant__ int c_ka[12] = {0,64,128,192, 256,320,384,448, 0,64,128,192};
__constant__ int c_kb[12] = {0,64,128,192, 0,64,128,192, 256,320,384,448};

// ---------------- helpers ----------------
static __device__ __forceinline__ void split1(float x, __nv_bfloat16& h, __nv_bfloat16& l) {
    h = __float2bfloat16(x);
    l = __float2bfloat16(x - __bfloat162float(h));
}
static __device__ __forceinline__ uint2 pack4(__nv_bfloat16 a, __nv_bfloat16 b,
                                              __nv_bfloat16 c, __nv_bfloat16 d) {
    uint2 u;
    u.x = ((uint32_t)__bfloat16_as_ushort(b) << 16) | __bfloat16_as_ushort(a);
    u.y = ((uint32_t)__bfloat16_as_ushort(d) << 16) | __bfloat16_as_ushort(c);
    return u;
}

// ---------------- fused hamilton build + h|l split ----------------
__global__ void build_ham_split(const float* __restrict__ W, __nv_bfloat16* __restrict__ out,
                                int off) {
    int idx = blockIdx.x * blockDim.x + threadIdx.x;
    if (idx >= EMB * EMB) return;
    int c = idx >> 8, k = idx & 255;
    int a = k >> 6, u = k & 63, b = c >> 6, v = c & 63;
    float val = c_sign[a][b] * W[u * EMB + c_comp[a][b] * 64 + v];
    __nv_bfloat16 h, l;
    split1(val, h, l);
    size_t base = (size_t)(off + c) * KS2;
    out[base + k] = h;
    out[base + 256 + k] = l;
}

__global__ void build_lin_split(const float* __restrict__ W, __nv_bfloat16* __restrict__ o1,
                                __nv_bfloat16* __restrict__ o2) {
    int c = blockIdx.x, j = threadIdx.x;
    int q = j >> 6, s = j & 63;
    int b = c >> 6, v = c & 63;
    int pe = 128 * q + s;
    int pr = pe + 64;
    int a1 = pe >> 7, u1 = pe & 127;
    int a2 = pr >> 7, u2 = pr & 127;
    float v1 = c_sign[a1][b] * W[u1 * EMB + c_comp[a1][b] * 64 + v];
    float v2 = c_sign[a2][b] * W[u2 * EMB + c_comp[a2][b] * 64 + v];
    __nv_bfloat16 h, l;
    size_t base = (size_t)c * KS2;
    split1(v1, h, l); o1[base + j] = h; o1[base + 256 + j] = l;
    split1(v2, h, l); o2[base + j] = h; o2[base + 256 + j] = l;
}

// ---------------- h|l split conversion ----------------
__global__ void split_hl(const float* __restrict__ in, __nv_bfloat16* __restrict__ out,
                         int n64) {
    int i = blockIdx.x * blockDim.x + threadIdx.x;
    if (i >= n64) return;
    int r = i >> 6, c4 = (i & 63) << 2;
    float4 x = *(const float4*)(in + (size_t)r * EMB + c4);
    __nv_bfloat16 h[4], l[4];
    split1(x.x, h[0], l[0]); split1(x.y, h[1], l[1]);
    split1(x.z, h[2], l[2]); split1(x.w, h[3], l[3]);
    size_t b = (size_t)r * KS2 + c4;
    *(uint2*)(out + b) = pack4(h[0], h[1], h[2], h[3]);
    *(uint2*)(out + b + 256) = pack4(l[0], l[1], l[2], l[3]);
}

// merged split of both agg buffers (one launch)
__global__ void split_hl2(const float* __restrict__ in1, __nv_bfloat16* __restrict__ out1,
                          const float* __restrict__ in2, __nv_bfloat16* __restrict__ out2,
                          int n1_64, int n2_64) {
    int i = blockIdx.x * blockDim.x + threadIdx.x;
    const float* in;
    __nv_bfloat16* out;
    if (i < n1_64) { in = in1; out = out1; }
    else { i -= n1_64; if (i >= n2_64) return; in = in2; out = out2; }
    int r = i >> 6, c4 = (i & 63) << 2;
    float4 x = *(const float4*)(in + (size_t)r * EMB + c4);
    __nv_bfloat16 h[4], l[4];
    split1(x.x, h[0], l[0]); split1(x.y, h[1], l[1]);
    split1(x.z, h[2], l[2]); split1(x.w, h[3], l[3]);
    size_t b = (size_t)r * KS2 + c4;
    *(uint2*)(out + b) = pack4(h[0], h[1], h[2], h[3]);
    *(uint2*)(out + b + 256) = pack4(l[0], l[1], l[2], l[3]);
}

// bn+tanh fused with h|l split output.
// WRR: write float rows >= N_ENTS into XRout (the R-row update)
template <bool WRR>
__global__ void bn_tanh_split(const float* __restrict__ X, float* __restrict__ XRout,
                              __nv_bfloat16* __restrict__ out, int so, int n64) {
    int i = blockIdx.x * blockDim.x + threadIdx.x;
    if (i >= n64) return;
    int r = i >> 6, c4 = (i & 63) << 2;
    float4 x = *(const float4*)(X + (size_t)r * EMB + c4);
    float y[4];
    float* xs = &x.x;
#pragma unroll
    for (int j = 0; j < 4; j++) {
        float z = xs[j] * g_scale[so + c4 + j] + g_shift[so + c4 + j];
        float e = __expf(-2.f * fabsf(z));
        float t = (1.f - e) / (1.f + e);
        y[j] = copysignf(t, z);
    }
    if (WRR && r >= N_ENTS)
        *(float4*)(XRout + (size_t)r * EMB + c4) = make_float4(y[0], y[1], y[2], y[3]);
    __nv_bfloat16 h[4], l[4];
#pragma unroll
    for (int j = 0; j < 4; j++) split1(y[j], h[j], l[j]);
    size_t b = (size_t)r * KS2 + c4;
    *(uint2*)(out + b) = pack4(h[0], h[1], h[2], h[3]);
    *(uint2*)(out + b + 256) = pack4(l[0], l[1], l[2], l[3]);
}

// ====== bf16 HMMA GEMM: 128x128 tile, 64x32 warps, 3-stage, 2 CTA/SM ======
// DUAL: 24 chunks — 0-11 from (A,B), 12-23 from (A+dA, B+dB); accumulates both products.
enum { EPI_STORE = 0, EPI_SIG = 2 };

#define BM 128
#define BN 128
#define STAGE_SZ 32768            // A 16KB + B 16KB
#define SM_GEMM (3 * STAGE_SZ)    // 98304

static __device__ __forceinline__ uint32_t cvtas(const void* p) {
    uint32_t a;
    asm("{ .reg .u64 t; cvta.to.shared.u64 t, %1; cvt.u32.u64 %0, t; }" : "=r"(a) : "l"(p));
    return a;
}
static __device__ __forceinline__ uint32_t swz(uint32_t o) { return o ^ ((o >> 3) & 0x70); }
static __device__ __forceinline__ void cp16(uint32_t d, const void* g, int sz) {
    asm volatile("cp.async.cg.shared.global [%0], [%1], 16, %2;" :: "r"(d), "l"(g), "r"(sz));
}
static __device__ __forceinline__ void ldsm4(uint32_t& d0, uint32_t& d1, uint32_t& d2,
                                             uint32_t& d3, uint32_t a) {
    asm volatile("ldmatrix.sync.aligned.m8n8.x4.shared.b16 {%0,%1,%2,%3}, [%4];"
                 : "=r"(d0), "=r"(d1), "=r"(d2), "=r"(d3) : "r"(a));
}
static __device__ __forceinline__ void mma16816(float* c, uint32_t a0, uint32_t a1,
                                                uint32_t a2, uint32_t a3,
                                                uint32_t b0, uint32_t b1) {
    asm volatile("mma.sync.aligned.m16n8k16.row.col.f32.bf16.bf16.f32 "
                 "{%0,%1,%2,%3}, {%4,%5,%6,%7}, {%8,%9}, {%0,%1,%2,%3};"
                 : "+f"(c[0]), "+f"(c[1]), "+f"(c[2]), "+f"(c[3])
                 : "r"(a0), "r"(a1), "r"(a2), "r"(a3), "r"(b0), "r"(b1));
}

template <int EPI, bool DUAL>
__global__ void __launch_bounds__(256, 2)
gemm_bf16(const __nv_bfloat16* __restrict__ A, const __nv_bfloat16* __restrict__ B,
          const __nv_bfloat16* __restrict__ A2, const __nv_bfloat16* __restrict__ B2,
          float* __restrict__ C, int M, int N) {
    extern __shared__ char smem[];
    const uint32_t sb = cvtas(smem);
    const uint32_t stB[3] = { sb, sb + STAGE_SZ, sb + 2 * STAGE_SZ };
    const int NKC = DUAL ? 24 : 12;

    const int tid = threadIdx.x;
    const int lane = tid & 31, wid = tid >> 5;
    const int wm = wid >> 2, wn = wid & 3;
    const int m0 = blockIdx.y * BM, n0 = blockIdx.x * BN;

    const int r0 = tid >> 2;
    const int c2 = (tid & 3) * 2;
    uint32_t soff[2][2];
#pragma unroll
    for (int r = 0; r < 2; r++)
#pragma unroll
        for (int q = 0; q < 2; q++)
            soff[r][q] = swz((uint32_t)(r0 + r * 64) * 128 + (uint32_t)(c2 + q) * 16);

    int szA[2], szB[2];
    const __nv_bfloat16 *Ag[2], *Bg[2];
#pragma unroll
    for (int r = 0; r < 2; r++) {
        long mr = m0 + r0 + r * 64, nr = n0 + r0 + r * 64;
        szA[r] = mr < M ? 16 : 0;
        szB[r] = nr < N ? 16 : 0;
        Ag[r] = A + (size_t)(mr < M ? mr : M - 1) * KS2 + c2 * 8;
        Bg[r] = B + (size_t)(nr < N ? nr : N - 1) * KS2 + c2 * 8;
    }
    const ptrdiff_t dA = DUAL ? (A2 - A) : 0;
    const ptrdiff_t dB = DUAL ? (B2 - B) : 0;

    float acc[4][4][4];
#pragma unroll
    for (int i = 0; i < 4; i++)
#pragma unroll
        for (int j = 0; j < 4; j++)
#pragma unroll
            for (int q = 0; q < 4; q++) acc[i][j][q] = 0.f;

    auto issue = [&](uint32_t stBase, int kc) {
        const bool p2 = DUAL && (kc >= 12);
        const int kcm = p2 ? kc - 12 : kc;
        const int ka = c_ka[kcm], kb = c_kb[kcm];
        const ptrdiff_t oa = p2 ? dA : 0, ob = p2 ? dB : 0;
        const uint32_t aB = stBase, bB_ = stBase + 16384;
#pragma unroll
        for (int q = 0; q < 2; q++)
#pragma unroll
            for (int r = 0; r < 2; r++) {
                cp16(aB + soff[r][q], Ag[r] + oa + ka + q * 8, szA[r]);
                cp16(bB_ + soff[r][q], Bg[r] + ob + kb + q * 8, szB[r]);
            }
        asm volatile("cp.async.commit_group;");
    };

    const uint32_t aRow = (uint32_t)(wm * 64 + (lane & 15));
    const uint32_t aChk = (uint32_t)(lane >> 4);
    const uint32_t bRow0 = (uint32_t)(wn * 32 + (lane & 7) + ((lane >> 4) & 1) * 8);
    const uint32_t bChk = (uint32_t)((lane >> 3) & 1);

    auto compute = [&](uint32_t stBase) {
        const uint32_t aB = stBase, bB_ = stBase + 16384;
#pragma unroll
        for (int ks = 0; ks < 4; ks++) {
            uint32_t a[4][4];
#pragma unroll
            for (int mi = 0; mi < 4; mi++) {
                uint32_t o = (aRow + mi * 16) * 128 + (2 * ks + aChk) * 16;
                ldsm4(a[mi][0], a[mi][1], a[mi][2], a[mi][3], aB + swz(o));
            }
            uint32_t bf[4][2];
#pragma unroll
            for (int j = 0; j < 2; j++) {
                uint32_t t0, t1, t2, t3;
                uint32_t o = (bRow0 + j * 16) * 128 + (2 * ks + bChk) * 16;
                ldsm4(t0, t1, t2, t3, bB_ + swz(o));
                bf[2 * j][0] = t0;     bf[2 * j][1] = t1;
                bf[2 * j + 1][0] = t2; bf[2 * j + 1][1] = t3;
            }
#pragma unroll
            for (int mi = 0; mi < 4; mi++)
#pragma unroll
                for (int nj = 0; nj < 4; nj++)
                    mma16816(acc[mi][nj], a[mi][0], a[mi][1], a[mi][2], a[mi][3],
                             bf[nj][0], bf[nj][1]);
        }
    };

    issue(stB[0], 0);
    issue(stB[1], 1);
    auto step = [&](int kc, int st) {
        asm volatile("cp.async.wait_group 1;");
        __syncthreads();
        compute(stB[st]);
        if (kc + 2 < NKC) issue(stB[(st + 2) % 3], kc + 2);
        else asm volatile("cp.async.commit_group;");
    };
#pragma unroll 1
    for (int kc = 0; kc < NKC; kc += 3) {
        step(kc, 0); step(kc + 1, 1); step(kc + 2, 2);
    }

    // epilogue
#pragma unroll
    for (int mi = 0; mi < 4; mi++) {
        int row = m0 + wm * 64 + mi * 16 + (lane >> 2);
#pragma unroll
        for (int nj = 0; nj < 4; nj++) {
            int col = n0 + wn * 32 + nj * 8 + (lane & 3) * 2;
            float* cf = acc[mi][nj];
#pragma unroll
            for (int h = 0; h < 2; h++) {
                int r = row + h * 8;
                if (r >= M) continue;
                float* p = C + (size_t)r * N + col;
#pragma unroll
                for (int q = 0; q < 2; q++) {
                    if (col + q >= N) continue;
                    float v = cf[h * 2 + q];
                    if (EPI == EPI_SIG) v = 1.f / (1.f + __expf(-v));
                    p[q] = v;
                }
            }
        }
    }
}

// ---------------- merged SpMM over both graphs, gathering from XR directly ------------
// (segsum commutes with the GEMM: agg' = segsum(vals, X[cols]); Y = agg' @ H)
__global__ void spmm2(const int* __restrict__ r1, const int* __restrict__ c1,
                      const float* __restrict__ v1,
                      const int* __restrict__ r2, const int* __restrict__ c2,
                      const float* __restrict__ v2,
                      const float* __restrict__ X,
                      float* __restrict__ a1, float* __restrict__ a2) {
    int e = blockIdx.x * 4 + (threadIdx.x >> 6);
    int t = threadIdx.x & 63;
    const int *R, *C;
    const float *V;
    float* A;
    if (e < N_EDGES) { R = r1; C = c1; V = v1; A = a1; }
    else { e -= N_EDGES; if (e >= N_EDGES) return; R = r2; C = c2; V = v2; A = a2; }
    int r = R[e], c = C[e];
    float v = V[e];
    float4 s = *(const float4*)(X + (size_t)c * EMB + t * 4);
    float4 a = make_float4(v * s.x, v * s.y, v * s.z, v * s.w);
    atomicAdd((float4*)(A + (size_t)r * EMB + t * 4), a);
}

// ---------------- merged node batchnorm stats (both branches) ----------------
#define NB_XR 198   // ceil(N_TOT/256)
#define NB_X  196   // ceil(N_ENTS/256)
__global__ void colstats2(const float* __restrict__ aggXR, const float* __restrict__ aggX) {
    int c = threadIdx.x;
    int b = blockIdx.x;
    const float* X;
    int r0, r1, off;
    if (b < NB_XR) { X = aggXR; r0 = b * 256; r1 = min(r0 + 256, N_TOT); off = 0; }
    else { X = aggX; r0 = (b - NB_XR) * 256; r1 = min(r0 + 256, N_ENTS); off = 256; }
    float s = 0.f, s2 = 0.f;
    for (int r = r0; r < r1; r++) {
        float v = X[(size_t)r * EMB + c];
        s += v; s2 += v * v;
    }
    atomicAdd(&g_csum[off + c], s);
    atomicAdd(&g_csq[off + c], s2);
}

__global__ void bn_final2(const float* __restrict__ g2g, const float* __restrict__ g2b,
                          const float* __restrict__ g1g, const float* __restrict__ g1b) {
    int c = threadIdx.x;   // 0..511
    float inv_n = c < 256 ? (1.f / N_TOT) : (1.f / N_ENTS);
    float gam = c < 256 ? g2g[c] : g1g[c - 256];
    float bet = c < 256 ? g2b[c] : g1b[c - 256];
    float m = g_csum[c] * inv_n;
    float var = g_csq[c] * inv_n - m * m;
    float sc = rsqrtf(var + BN_EPS) * gam;
    g_scale[c] = sc;
    g_shift[c] = bet - m * sc;
}

// ---------------- score head ----------------
__global__ void vecvec(const float* __restrict__ X, const float* __restrict__ R,
                       const int* __restrict__ e1, const int* __restrict__ ri,
                       float* __restrict__ hr) {
    int b = blockIdx.x;
    int s = threadIdx.x;
    const float* h = X + (size_t)e1[b] * EMB;
    const float* p = R + (size_t)ri[b] * EMB;
    float pr = p[s], pi = p[64 + s], pj = p[128 + s], pk = p[192 + s];
    float inv = rsqrtf(pr * pr + pi * pi + pj * pj + pk * pk);
    pr *= inv; pi *= inv; pj *= inv; pk *= inv;
    float qr = h[s], qi = h[64 + s], qj = h[128 + s], qk = h[192 + s];
    float* o = hr + (size_t)b * EMB;
    o[s]       = qr * pr - qi * pi - qj * pj - qk * pk;
    o[64 + s]  = qi * pr + qr * pi - qk * pj + qj * pk;
    o[128 + s] = qj * pr + qk * pi + qr * pj - qi * pk;
    o[192 + s] = qk * pr - qj * pi + qi * pj + qr * pk;
}

__global__ void __launch_bounds__(1024)
bn_batch(float* __restrict__ hr, const float* __restrict__ gamma,
         const float* __restrict__ beta) {
    __shared__ float ss[4][EMB], sq[4][EMB], sc[EMB], sh[EMB];
    int c = threadIdx.x & 255, g = threadIdx.x >> 8;
    float s = 0.f, s2 = 0.f;
    for (int b = g * 128; b < g * 128 + 128; b++) {
        float v = hr[(size_t)b * EMB + c];
        s += v; s2 += v * v;
    }
    ss[g][c] = s; sq[g][c] = s2;
    __syncthreads();
    if (g == 0) {
        float S = ss[0][c] + ss[1][c] + ss[2][c] + ss[3][c];
        float Q = sq[0][c] + sq[1][c] + sq[2][c] + sq[3][c];
        float m = S * (1.f / BATCH);
        float var = Q * (1.f / BATCH) - m * m;
        float scale = rsqrtf(var + BN_EPS) * gamma[c];
        sc[c] = scale; sh[c] = beta[c] - m * scale;
    }
    __syncthreads();
    float scale = sc[c], shift = sh[c];
    for (int b = g * 128; b < g * 128 + 128; b++)
        hr[(size_t)b * EMB + c] = hr[(size_t)b * EMB + c] * scale + shift;
}

// ---------------- host orchestration ----------------
extern "C" void kernel_launch(void* const* d_in, const int* in_sizes, int n_in,
                              void* d_out, int out_size) {
    const int*   e1      = (const int*)d_in[0];
    const int*   ri      = (const int*)d_in[1];
    const float* emb     = (const float*)d_in[2];
    const float* gcn1_w  = (const float*)d_in[3];
    const float* gcn2_w  = (const float*)d_in[4];
    const float* g1_gam  = (const float*)d_in[5];
    const float* g1_bet  = (const float*)d_in[6];
    const float* g2_gam  = (const float*)d_in[7];
    const float* g2_bet  = (const float*)d_in[8];
    const float* lin     = (const float*)d_in[9];
    const float* bsg     = (const float*)d_in[10];
    const float* bsb     = (const float*)d_in[11];
    const int*   a_rows  = (const int*)d_in[12];
    const int*   a_cols  = (const int*)d_in[13];
    const float* a_vals  = (const float*)d_in[14];
    const int*   ar_rows = (const int*)d_in[15];
    const int*   ar_cols = (const int*)d_in[16];
    const float* ar_vals = (const float*)d_in[17];
    float* out = (float*)d_out;

    cudaFuncSetAttribute(gemm_bf16<EPI_STORE, false>, cudaFuncAttributeMaxDynamicSharedMemorySize, SM_GEMM);
    cudaFuncSetAttribute(gemm_bf16<EPI_STORE, true>,  cudaFuncAttributeMaxDynamicSharedMemorySize, SM_GEMM);
    cudaFuncSetAttribute(gemm_bf16<EPI_SIG, false>,   cudaFuncAttributeMaxDynamicSharedMemorySize, SM_GEMM);

    static cudaStream_t s_side = nullptr;
    static cudaEvent_t evA[2], evV[2], evS[2];
    if (!s_side) {
        cudaStreamCreateWithFlags(&s_side, cudaStreamNonBlocking);
        for (int i = 0; i < 2; i++) {
            cudaEventCreateWithFlags(&evA[i], cudaEventDisableTiming);
            cudaEventCreateWithFlags(&evV[i], cudaEventDisableTiming);
            cudaEventCreateWithFlags(&evS[i], cudaEventDisableTiming);
        }
    }

    float *XR, *agg, *aggX, *hr, *csum, *csq;
    __nv_bfloat16 *SA1, *SA2, *SA3, *WbC, *Wb, *Wb2, *hrA;
    cudaGetSymbolAddress((void**)&XR,   g_XR);
    cudaGetSymbolAddress((void**)&agg,  g_agg);
    cudaGetSymbolAddress((void**)&aggX, g_aggX);
    cudaGetSymbolAddress((void**)&hr,   g_hr);
    cudaGetSymbolAddress((void**)&csum, g_csum);
    cudaGetSymbolAddress((void**)&csq,  g_csq);
    cudaGetSymbolAddress((void**)&SA1,  g_SA1);
    cudaGetSymbolAddress((void**)&SA2,  g_SA2);
    cudaGetSymbolAddress((void**)&SA3,  g_SA3);
    cudaGetSymbolAddress((void**)&WbC,  g_WbC);
    cudaGetSymbolAddress((void**)&Wb,   g_Wb);
    cudaGetSymbolAddress((void**)&Wb2,  g_Wb2);
    cudaGetSymbolAddress((void**)&hrA,  g_hrA);

    cudaMemcpyAsync(XR, emb, (size_t)N_TOT * EMB * sizeof(float),
                    cudaMemcpyDeviceToDevice);

    const dim3 gWt(2, (N_TOT + BM - 1) / BM);       // N_TOT x 256 GEMM
    const dim3 gWe(2, (N_ENTS + BM - 1) / BM);      // N_ENTS x 256 GEMM
    const dim3 gS((N_ENTS + BN - 1) / BN, (BATCH + BM - 1) / BM);
    const int BLK_TOT = (N_TOT * 64 + 255) / 256;
    const int BLK_ENT = (N_ENTS * 64 + 255) / 256;
    const int BLK_BOTH = (N_TOT * 64 + N_ENTS * 64 + 255) / 256;
    const int BLK_HAM = (EMB * EMB + 255) / 256;

    // prologue
    split_hl<<<BLK_TOT, 256>>>(XR, SA1, N_TOT * 64);
    cudaEventRecord(evA[0], 0);   // XR + SA1 ready for score 0
    build_ham_split<<<BLK_HAM, 256>>>(gcn2_w, WbC, 0);
    build_ham_split<<<BLK_HAM, 256>>>(gcn1_w, WbC, 256);

    for (int l = 0; l < 2; l++) {
        if (l > 0) {
            build_ham_split<<<BLK_HAM, 256>>>(gcn2_w + (size_t)l * 64 * EMB, WbC, 0);
            build_ham_split<<<BLK_HAM, 256>>>(gcn1_w + (size_t)l * 64 * EMB, WbC, 256);
        }

        // ---- side: score(l) overlapped with the spmm chain ----
        cudaStreamWaitEvent(s_side, evA[l], 0);
        vecvec<<<BATCH, 64, 0, s_side>>>(XR, XR + (size_t)N_ENTS * EMB, e1, ri, hr);
        cudaEventRecord(evV[l], s_side);              // XR no longer read by side
        bn_batch<<<1, 1024, 0, s_side>>>(hr, bsg + l * EMB, bsb + l * EMB);
        split_hl<<<(BATCH * 64 + 255) / 256, 256, 0, s_side>>>(hr, hrA, BATCH * 64);
        gemm_bf16<EPI_SIG, false><<<gS, 256, SM_GEMM, s_side>>>(
            hrA, SA1, nullptr, nullptr, out + (size_t)l * BATCH * N_ENTS, BATCH, N_ENTS);
        cudaEventRecord(evS[l], s_side);              // SA1 no longer read by side

        // ---- main: segsum FIRST (gathers from XR, L2-resident) ----
        cudaMemsetAsync(agg,  0, (size_t)N_TOT * EMB * sizeof(float));
        cudaMemsetAsync(aggX, 0, (size_t)N_ENTS * EMB * sizeof(float));
        spmm2<<<(2 * N_EDGES + 3) / 4, 256>>>(ar_rows, ar_cols, ar_vals,
                                              a_rows, a_cols, a_vals,
                                              XR, agg, aggX);
        // split both aggs, then apply gcn weights (Y overwrites agg buffers)
        split_hl2<<<BLK_BOTH, 256>>>(agg, SA2, aggX, SA3, N_TOT * 64, N_ENTS * 64);
        gemm_bf16<EPI_STORE, false><<<gWt, 256, SM_GEMM>>>(SA2, WbC, nullptr, nullptr,
                                                           agg, N_TOT, EMB);
        gemm_bf16<EPI_STORE, false><<<gWe, 256, SM_GEMM>>>(SA3, WbC + 256 * KS2,
                                                           nullptr, nullptr,
                                                           aggX, N_ENTS, EMB);
        // stats + activation
        cudaMemsetAsync(csum, 0, 2 * EMB * sizeof(float));
        cudaMemsetAsync(csq,  0, 2 * EMB * sizeof(float));
        colstats2<<<NB_XR + NB_X, EMB>>>(agg, aggX);
        bn_final2<<<1, 2 * EMB>>>(g2_gam + l * EMB, g2_bet + l * EMB,
                                  g1_gam + l * EMB, g1_bet + l * EMB);
        cudaStreamWaitEvent(0, evV[l], 0);            // side done reading XR
        bn_tanh_split<true><<<BLK_TOT, 256>>>(agg, XR, SA2, 0, N_TOT * 64);
        bn_tanh_split<false><<<BLK_ENT, 256>>>(aggX, nullptr, SA3, 256, N_ENTS * 64);

        // ---- main: fused lin: X_new = Xef @ H1^T + Xrf @ H2^T (24-chunk dual) ----
        build_lin_split<<<EMB, EMB>>>(lin + (size_t)l * 128 * EMB, Wb, Wb2);
        gemm_bf16<EPI_STORE, true><<<gWe, 256, SM_GEMM>>>(SA3, Wb, SA2, Wb2,
                                                          XR, N_ENTS, EMB);

        cudaStreamWaitEvent(0, evS[l], 0);            // side done reading SA1 (joins side)
        split_hl<<<BLK_TOT, 256>>>(XR, SA1, N_TOT * 64);
        if (l == 0) cudaEventRecord(evA[1], 0);       // ready for score 1
    }

    // final score on main (terminal)
    vecvec<<<BATCH, 64>>>(XR, XR + (size_t)N_ENTS * EMB, e1, ri, hr);
    bn_batch<<<1, 1024>>>(hr, bsg + 2 * EMB, bsb + 2 * EMB);
    split_hl<<<(BATCH * 64 + 255) / 256, 256>>>(hr, hrA, BATCH * 64);
    gemm_bf16<EPI_SIG, false><<<gS, 256, SM_GEMM>>>(
        hrA, SA1, nullptr, nullptr, out + (size_t)2 * BATCH * N_ENTS, BATCH, N_ENTS);
}

// round 13
// speedup vs baseline: 1.0790x; 1.0790x over previous
#include <cuda_runtime.h>
#include <cuda_bf16.h>
#include <stdint.h>

#define N_ENTS 50000
#define N_RELS 500
#define N_TOT  50500
#define EMB    256
#define N_EDGES 400000
#define BATCH  512
#define BN_EPS 1e-5f
#define KS2    512   // h|l storage width (bf16x3 streams 768 via chunk tables)

// ---------------- scratch (__device__ globals, no allocations) ----------------
__device__ float g_XR[(size_t)N_TOT * EMB];
__device__ float g_supC[(size_t)N_TOT * 2 * EMB];   // fused support: cols 0-255 XR-branch, 256-511 X-branch
__device__ float g_agg[(size_t)N_TOT * EMB];        // XR-branch segment sum
__device__ float g_aggX[(size_t)N_ENTS * EMB];      // X-branch segment sum
__device__ float g_hr[(size_t)BATCH * EMB];
__device__ float g_csum[2 * EMB];
__device__ float g_csq[2 * EMB];
__device__ float g_scale[2 * EMB];
__device__ float g_shift[2 * EMB];

// h|l split buffers: [n, 512] bf16, cols 0-255 = hi, 256-511 = lo
__device__ __nv_bfloat16 g_SA1[(size_t)N_TOT * KS2];     // split of XR
__device__ __nv_bfloat16 g_SA2[(size_t)N_TOT * KS2];     // split of XRrf
__device__ __nv_bfloat16 g_SA3[(size_t)N_ENTS * KS2];    // split of Xef
__device__ __nv_bfloat16 g_WbC[512 * KS2];               // fused gcn weights (512 out cols)
__device__ __nv_bfloat16 g_Wb[EMB * KS2];                // lin weights H1
__device__ __nv_bfloat16 g_Wb2[EMB * KS2];               // lin weights H2
__device__ __nv_bfloat16 g_hrA[(size_t)BATCH * KS2];     // split hr

// quaternion block tables
__constant__ int   c_comp[4][4] = {{0,1,2,3},{1,0,3,2},{2,3,0,1},{3,2,1,0}};
__constant__ float c_sign[4][4] = {{ 1.f, 1.f, 1.f, 1.f},
                                   {-1.f, 1.f, 1.f,-1.f},
                                   {-1.f,-1.f, 1.f, 1.f},
                                   {-1.f, 1.f,-1.f, 1.f}};

// bf16x3 chunk schedule (64-half chunks): AhBh x4, AlBh x4, AhBl x4
__constant__ int c_ka[12] = {0,64,128,192, 256,320,384,448, 0,64,128,192};
__constant__ int c_kb[12] = {0,64,128,192, 0,64,128,192, 256,320,384,448};

// ---------------- helpers ----------------
static __device__ __forceinline__ void split1(float x, __nv_bfloat16& h, __nv_bfloat16& l) {
    h = __float2bfloat16(x);
    l = __float2bfloat16(x - __bfloat162float(h));
}
static __device__ __forceinline__ uint2 pack4(__nv_bfloat16 a, __nv_bfloat16 b,
                                              __nv_bfloat16 c, __nv_bfloat16 d) {
    uint2 u;
    u.x = ((uint32_t)__bfloat16_as_ushort(b) << 16) | __bfloat16_as_ushort(a);
    u.y = ((uint32_t)__bfloat16_as_ushort(d) << 16) | __bfloat16_as_ushort(c);
    return u;
}

// ---------------- fused hamilton build + h|l split ----------------
__global__ void build_ham_split(const float* __restrict__ W, __nv_bfloat16* __restrict__ out,
                                int off) {
    int idx = blockIdx.x * blockDim.x + threadIdx.x;
    if (idx >= EMB * EMB) return;
    int c = idx >> 8, k = idx & 255;
    int a = k >> 6, u = k & 63, b = c >> 6, v = c & 63;
    float val = c_sign[a][b] * W[u * EMB + c_comp[a][b] * 64 + v];
    __nv_bfloat16 h, l;
    split1(val, h, l);
    size_t base = (size_t)(off + c) * KS2;
    out[base + k] = h;
    out[base + 256 + k] = l;
}

__global__ void build_lin_split(const float* __restrict__ W, __nv_bfloat16* __restrict__ o1,
                                __nv_bfloat16* __restrict__ o2) {
    int c = blockIdx.x, j = threadIdx.x;
    int q = j >> 6, s = j & 63;
    int b = c >> 6, v = c & 63;
    int pe = 128 * q + s;
    int pr = pe + 64;
    int a1 = pe >> 7, u1 = pe & 127;
    int a2 = pr >> 7, u2 = pr & 127;
    float v1 = c_sign[a1][b] * W[u1 * EMB + c_comp[a1][b] * 64 + v];
    float v2 = c_sign[a2][b] * W[u2 * EMB + c_comp[a2][b] * 64 + v];
    __nv_bfloat16 h, l;
    size_t base = (size_t)c * KS2;
    split1(v1, h, l); o1[base + j] = h; o1[base + 256 + j] = l;
    split1(v2, h, l); o2[base + j] = h; o2[base + 256 + j] = l;
}

// ---------------- h|l split conversion ----------------
__global__ void split_hl(const float* __restrict__ in, __nv_bfloat16* __restrict__ out,
                         int n64) {
    int i = blockIdx.x * blockDim.x + threadIdx.x;
    if (i >= n64) return;
    int r = i >> 6, c4 = (i & 63) << 2;
    float4 x = *(const float4*)(in + (size_t)r * EMB + c4);
    __nv_bfloat16 h[4], l[4];
    split1(x.x, h[0], l[0]); split1(x.y, h[1], l[1]);
    split1(x.z, h[2], l[2]); split1(x.w, h[3], l[3]);
    size_t b = (size_t)r * KS2 + c4;
    *(uint2*)(out + b) = pack4(h[0], h[1], h[2], h[3]);
    *(uint2*)(out + b + 256) = pack4(l[0], l[1], l[2], l[3]);
}

// merged bn+tanh+split for BOTH branches in one launch.
// part 1 (i < n1_64): agg -> SA2, scale offset 0, R-rows written to XRout.
// part 2:             aggX -> SA3, scale offset 256.
__global__ void bn_tanh_split2(const float* __restrict__ in1, float* __restrict__ XRout,
                               __nv_bfloat16* __restrict__ out1,
                               const float* __restrict__ in2,
                               __nv_bfloat16* __restrict__ out2,
                               int n1_64, int n2_64) {
    int i = blockIdx.x * blockDim.x + threadIdx.x;
    const float* in;
    __nv_bfloat16* out;
    int so;
    bool wrr;
    if (i < n1_64) { in = in1; out = out1; so = 0; wrr = true; }
    else { i -= n1_64; if (i >= n2_64) return; in = in2; out = out2; so = 256; wrr = false; }
    int r = i >> 6, c4 = (i & 63) << 2;
    float4 x = *(const float4*)(in + (size_t)r * EMB + c4);
    float y[4];
    float* xs = &x.x;
#pragma unroll
    for (int j = 0; j < 4; j++) {
        float z = xs[j] * g_scale[so + c4 + j] + g_shift[so + c4 + j];
        float e = __expf(-2.f * fabsf(z));
        float t = (1.f - e) / (1.f + e);
        y[j] = copysignf(t, z);
    }
    if (wrr && r >= N_ENTS)
        *(float4*)(XRout + (size_t)r * EMB + c4) = make_float4(y[0], y[1], y[2], y[3]);
    __nv_bfloat16 h[4], l[4];
#pragma unroll
    for (int j = 0; j < 4; j++) split1(y[j], h[j], l[j]);
    size_t b = (size_t)r * KS2 + c4;
    *(uint2*)(out + b) = pack4(h[0], h[1], h[2], h[3]);
    *(uint2*)(out + b + 256) = pack4(l[0], l[1], l[2], l[3]);
}

// ====== bf16 HMMA GEMM: 128x128 tile, 64x32 warps, 3-stage, 2 CTA/SM ======
// DUAL: 24 chunks — 0-11 from (A,B), 12-23 from (A+dA, B+dB); accumulates both products.
enum { EPI_STORE = 0, EPI_SIG = 2 };

#define BM 128
#define BN 128
#define STAGE_SZ 32768            // A 16KB + B 16KB
#define SM_GEMM (3 * STAGE_SZ)    // 98304

static __device__ __forceinline__ uint32_t cvtas(const void* p) {
    uint32_t a;
    asm("{ .reg .u64 t; cvta.to.shared.u64 t, %1; cvt.u32.u64 %0, t; }" : "=r"(a) : "l"(p));
    return a;
}
static __device__ __forceinline__ uint32_t swz(uint32_t o) { return o ^ ((o >> 3) & 0x70); }
static __device__ __forceinline__ void cp16(uint32_t d, const void* g, int sz) {
    asm volatile("cp.async.cg.shared.global [%0], [%1], 16, %2;" :: "r"(d), "l"(g), "r"(sz));
}
static __device__ __forceinline__ void ldsm4(uint32_t& d0, uint32_t& d1, uint32_t& d2,
                                             uint32_t& d3, uint32_t a) {
    asm volatile("ldmatrix.sync.aligned.m8n8.x4.shared.b16 {%0,%1,%2,%3}, [%4];"
                 : "=r"(d0), "=r"(d1), "=r"(d2), "=r"(d3) : "r"(a));
}
static __device__ __forceinline__ void mma16816(float* c, uint32_t a0, uint32_t a1,
                                                uint32_t a2, uint32_t a3,
                                                uint32_t b0, uint32_t b1) {
    asm volatile("mma.sync.aligned.m16n8k16.row.col.f32.bf16.bf16.f32 "
                 "{%0,%1,%2,%3}, {%4,%5,%6,%7}, {%8,%9}, {%0,%1,%2,%3};"
                 : "+f"(c[0]), "+f"(c[1]), "+f"(c[2]), "+f"(c[3])
                 : "r"(a0), "r"(a1), "r"(a2), "r"(a3), "r"(b0), "r"(b1));
}

template <int EPI, bool DUAL>
__global__ void __launch_bounds__(256, 2)
gemm_bf16(const __nv_bfloat16* __restrict__ A, const __nv_bfloat16* __restrict__ B,
          const __nv_bfloat16* __restrict__ A2, const __nv_bfloat16* __restrict__ B2,
          float* __restrict__ C, int M, int N) {
    extern __shared__ char smem[];
    const uint32_t sb = cvtas(smem);
    const uint32_t stB[3] = { sb, sb + STAGE_SZ, sb + 2 * STAGE_SZ };
    const int NKC = DUAL ? 24 : 12;

    const int tid = threadIdx.x;
    const int lane = tid & 31, wid = tid >> 5;
    const int wm = wid >> 2, wn = wid & 3;
    const int m0 = blockIdx.y * BM, n0 = blockIdx.x * BN;

    const int r0 = tid >> 2;
    const int c2 = (tid & 3) * 2;
    uint32_t soff[2][2];
#pragma unroll
    for (int r = 0; r < 2; r++)
#pragma unroll
        for (int q = 0; q < 2; q++)
            soff[r][q] = swz((uint32_t)(r0 + r * 64) * 128 + (uint32_t)(c2 + q) * 16);

    int szA[2], szB[2];
    const __nv_bfloat16 *Ag[2], *Bg[2];
#pragma unroll
    for (int r = 0; r < 2; r++) {
        long mr = m0 + r0 + r * 64, nr = n0 + r0 + r * 64;
        szA[r] = mr < M ? 16 : 0;
        szB[r] = nr < N ? 16 : 0;
        Ag[r] = A + (size_t)(mr < M ? mr : M - 1) * KS2 + c2 * 8;
        Bg[r] = B + (size_t)(nr < N ? nr : N - 1) * KS2 + c2 * 8;
    }
    const ptrdiff_t dA = DUAL ? (A2 - A) : 0;
    const ptrdiff_t dB = DUAL ? (B2 - B) : 0;

    float acc[4][4][4];
#pragma unroll
    for (int i = 0; i < 4; i++)
#pragma unroll
        for (int j = 0; j < 4; j++)
#pragma unroll
            for (int q = 0; q < 4; q++) acc[i][j][q] = 0.f;

    auto issue = [&](uint32_t stBase, int kc) {
        const bool p2 = DUAL && (kc >= 12);
        const int kcm = p2 ? kc - 12 : kc;
        const int ka = c_ka[kcm], kb = c_kb[kcm];
        const ptrdiff_t oa = p2 ? dA : 0, ob = p2 ? dB : 0;
        const uint32_t aB = stBase, bB_ = stBase + 16384;
#pragma unroll
        for (int q = 0; q < 2; q++)
#pragma unroll
            for (int r = 0; r < 2; r++) {
                cp16(aB + soff[r][q], Ag[r] + oa + ka + q * 8, szA[r]);
                cp16(bB_ + soff[r][q], Bg[r] + ob + kb + q * 8, szB[r]);
            }
        asm volatile("cp.async.commit_group;");
    };

    const uint32_t aRow = (uint32_t)(wm * 64 + (lane & 15));
    const uint32_t aChk = (uint32_t)(lane >> 4);
    const uint32_t bRow0 = (uint32_t)(wn * 32 + (lane & 7) + ((lane >> 4) & 1) * 8);
    const uint32_t bChk = (uint32_t)((lane >> 3) & 1);

    auto compute = [&](uint32_t stBase) {
        const uint32_t aB = stBase, bB_ = stBase + 16384;
#pragma unroll
        for (int ks = 0; ks < 4; ks++) {
            uint32_t a[4][4];
#pragma unroll
            for (int mi = 0; mi < 4; mi++) {
                uint32_t o = (aRow + mi * 16) * 128 + (2 * ks + aChk) * 16;
                ldsm4(a[mi][0], a[mi][1], a[mi][2], a[mi][3], aB + swz(o));
            }
            uint32_t bf[4][2];
#pragma unroll
            for (int j = 0; j < 2; j++) {
                uint32_t t0, t1, t2, t3;
                uint32_t o = (bRow0 + j * 16) * 128 + (2 * ks + bChk) * 16;
                ldsm4(t0, t1, t2, t3, bB_ + swz(o));
                bf[2 * j][0] = t0;     bf[2 * j][1] = t1;
                bf[2 * j + 1][0] = t2; bf[2 * j + 1][1] = t3;
            }
#pragma unroll
            for (int mi = 0; mi < 4; mi++)
#pragma unroll
                for (int nj = 0; nj < 4; nj++)
                    mma16816(acc[mi][nj], a[mi][0], a[mi][1], a[mi][2], a[mi][3],
                             bf[nj][0], bf[nj][1]);
        }
    };

    issue(stB[0], 0);
    issue(stB[1], 1);
    auto step = [&](int kc, int st) {
        asm volatile("cp.async.wait_group 1;");
        __syncthreads();
        compute(stB[st]);
        if (kc + 2 < NKC) issue(stB[(st + 2) % 3], kc + 2);
        else asm volatile("cp.async.commit_group;");
    };
#pragma unroll 1
    for (int kc = 0; kc < NKC; kc += 3) {
        step(kc, 0); step(kc + 1, 1); step(kc + 2, 2);
    }

    // epilogue
#pragma unroll
    for (int mi = 0; mi < 4; mi++) {
        int row = m0 + wm * 64 + mi * 16 + (lane >> 2);
#pragma unroll
        for (int nj = 0; nj < 4; nj++) {
            int col = n0 + wn * 32 + nj * 8 + (lane & 3) * 2;
            float* cf = acc[mi][nj];
#pragma unroll
            for (int h = 0; h < 2; h++) {
                int r = row + h * 8;
                if (r >= M) continue;
                float* p = C + (size_t)r * N + col;
#pragma unroll
                for (int q = 0; q < 2; q++) {
                    if (col + q >= N) continue;
                    float v = cf[h * 2 + q];
                    if (EPI == EPI_SIG) v = 1.f / (1.f + __expf(-v));
                    p[q] = v;
                }
            }
        }
    }
}

// ---------------- merged SpMM over both graphs (sup row stride = 512) ----------------
__global__ void spmm2(const int* __restrict__ r1, const int* __restrict__ c1,
                      const float* __restrict__ v1, const float* __restrict__ s1,
                      float* __restrict__ a1,
                      const int* __restrict__ r2, const int* __restrict__ c2,
                      const float* __restrict__ v2, const float* __restrict__ s2,
                      float* __restrict__ a2) {
    int e = blockIdx.x * 4 + (threadIdx.x >> 6);
    int t = threadIdx.x & 63;
    const int *R, *C;
    const float *V, *S;
    float* A;
    if (e < N_EDGES) { R = r1; C = c1; V = v1; S = s1; A = a1; }
    else { e -= N_EDGES; if (e >= N_EDGES) return; R = r2; C = c2; V = v2; S = s2; A = a2; }
    int r = R[e], c = C[e];
    float v = V[e];
    float4 s = *(const float4*)(S + (size_t)c * 512 + t * 4);
    float4 a = make_float4(v * s.x, v * s.y, v * s.z, v * s.w);
    atomicAdd((float4*)(A + (size_t)r * EMB + t * 4), a);
}

// ---------------- merged node batchnorm stats (both branches) ----------------
#define NB_XR 198   // ceil(N_TOT/256)
#define NB_X  196   // ceil(N_ENTS/256)
__global__ void colstats2(const float* __restrict__ aggXR, const float* __restrict__ aggX) {
    int c = threadIdx.x;
    int b = blockIdx.x;
    const float* X;
    int r0, r1, off;
    if (b < NB_XR) { X = aggXR; r0 = b * 256; r1 = min(r0 + 256, N_TOT); off = 0; }
    else { X = aggX; r0 = (b - NB_XR) * 256; r1 = min(r0 + 256, N_ENTS); off = 256; }
    float s = 0.f, s2 = 0.f;
    for (int r = r0; r < r1; r++) {
        float v = X[(size_t)r * EMB + c];
        s += v; s2 += v * v;
    }
    atomicAdd(&g_csum[off + c], s);
    atomicAdd(&g_csq[off + c], s2);
}

__global__ void bn_final2(const float* __restrict__ g2g, const float* __restrict__ g2b,
                          const float* __restrict__ g1g, const float* __restrict__ g1b) {
    int c = threadIdx.x;   // 0..511
    float inv_n = c < 256 ? (1.f / N_TOT) : (1.f / N_ENTS);
    float gam = c < 256 ? g2g[c] : g1g[c - 256];
    float bet = c < 256 ? g2b[c] : g1b[c - 256];
    float m = g_csum[c] * inv_n;
    float var = g_csq[c] * inv_n - m * m;
    float sc = rsqrtf(var + BN_EPS) * gam;
    g_scale[c] = sc;
    g_shift[c] = bet - m * sc;
}

// ---------------- score head ----------------
__global__ void vecvec(const float* __restrict__ X, const float* __restrict__ R,
                       const int* __restrict__ e1, const int* __restrict__ ri,
                       float* __restrict__ hr) {
    int b = blockIdx.x;
    int s = threadIdx.x;
    const float* h = X + (size_t)e1[b] * EMB;
    const float* p = R + (size_t)ri[b] * EMB;
    float pr = p[s], pi = p[64 + s], pj = p[128 + s], pk = p[192 + s];
    float inv = rsqrtf(pr * pr + pi * pi + pj * pj + pk * pk);
    pr *= inv; pi *= inv; pj *= inv; pk *= inv;
    float qr = h[s], qi = h[64 + s], qj = h[128 + s], qk = h[192 + s];
    float* o = hr + (size_t)b * EMB;
    o[s]       = qr * pr - qi * pi - qj * pj - qk * pk;
    o[64 + s]  = qi * pr + qr * pi - qk * pj + qj * pk;
    o[128 + s] = qj * pr + qk * pi + qr * pj - qi * pk;
    o[192 + s] = qk * pr - qj * pi + qi * pj + qr * pk;
}

__global__ void __launch_bounds__(1024)
bn_batch(float* __restrict__ hr, const float* __restrict__ gamma,
         const float* __restrict__ beta) {
    __shared__ float ss[4][EMB], sq[4][EMB], sc[EMB], sh[EMB];
    int c = threadIdx.x & 255, g = threadIdx.x >> 8;
    float s = 0.f, s2 = 0.f;
    for (int b = g * 128; b < g * 128 + 128; b++) {
        float v = hr[(size_t)b * EMB + c];
        s += v; s2 += v * v;
    }
    ss[g][c] = s; sq[g][c] = s2;
    __syncthreads();
    if (g == 0) {
        float S = ss[0][c] + ss[1][c] + ss[2][c] + ss[3][c];
        float Q = sq[0][c] + sq[1][c] + sq[2][c] + sq[3][c];
        float m = S * (1.f / BATCH);
        float var = Q * (1.f / BATCH) - m * m;
        float scale = rsqrtf(var + BN_EPS) * gamma[c];
        sc[c] = scale; sh[c] = beta[c] - m * scale;
    }
    __syncthreads();
    float scale = sc[c], shift = sh[c];
    for (int b = g * 128; b < g * 128 + 128; b++)
        hr[(size_t)b * EMB + c] = hr[(size_t)b * EMB + c] * scale + shift;
}

// ---------------- host orchestration ----------------
extern "C" void kernel_launch(void* const* d_in, const int* in_sizes, int n_in,
                              void* d_out, int out_size) {
    const int*   e1      = (const int*)d_in[0];
    const int*   ri      = (const int*)d_in[1];
    const float* emb     = (const float*)d_in[2];
    const float* gcn1_w  = (const float*)d_in[3];
    const float* gcn2_w  = (const float*)d_in[4];
    const float* g1_gam  = (const float*)d_in[5];
    const float* g1_bet  = (const float*)d_in[6];
    const float* g2_gam  = (const float*)d_in[7];
    const float* g2_bet  = (const float*)d_in[8];
    const float* lin     = (const float*)d_in[9];
    const float* bsg     = (const float*)d_in[10];
    const float* bsb     = (const float*)d_in[11];
    const int*   a_rows  = (const int*)d_in[12];
    const int*   a_cols  = (const int*)d_in[13];
    const float* a_vals  = (const float*)d_in[14];
    const int*   ar_rows = (const int*)d_in[15];
    const int*   ar_cols = (const int*)d_in[16];
    const float* ar_vals = (const float*)d_in[17];
    float* out = (float*)d_out;

    cudaFuncSetAttribute(gemm_bf16<EPI_STORE, false>, cudaFuncAttributeMaxDynamicSharedMemorySize, SM_GEMM);
    cudaFuncSetAttribute(gemm_bf16<EPI_STORE, true>,  cudaFuncAttributeMaxDynamicSharedMemorySize, SM_GEMM);
    cudaFuncSetAttribute(gemm_bf16<EPI_SIG, false>,   cudaFuncAttributeMaxDynamicSharedMemorySize, SM_GEMM);

    static cudaStream_t s_side = nullptr, s_mem = nullptr;
    static cudaEvent_t evF, evA[2], evV[2], evS[2], evM[2], evMd[2];
    if (!s_side) {
        cudaStreamCreateWithFlags(&s_side, cudaStreamNonBlocking);
        cudaStreamCreateWithFlags(&s_mem,  cudaStreamNonBlocking);
        cudaEventCreateWithFlags(&evF, cudaEventDisableTiming);
        for (int i = 0; i < 2; i++) {
            cudaEventCreateWithFlags(&evA[i],  cudaEventDisableTiming);
            cudaEventCreateWithFlags(&evV[i],  cudaEventDisableTiming);
            cudaEventCreateWithFlags(&evS[i],  cudaEventDisableTiming);
            cudaEventCreateWithFlags(&evM[i],  cudaEventDisableTiming);
            cudaEventCreateWithFlags(&evMd[i], cudaEventDisableTiming);
        }
    }

    float *XR, *supC, *agg, *aggX, *hr, *csum, *csq;
    __nv_bfloat16 *SA1, *SA2, *SA3, *WbC, *Wb, *Wb2, *hrA;
    cudaGetSymbolAddress((void**)&XR,   g_XR);
    cudaGetSymbolAddress((void**)&supC, g_supC);
    cudaGetSymbolAddress((void**)&agg,  g_agg);
    cudaGetSymbolAddress((void**)&aggX, g_aggX);
    cudaGetSymbolAddress((void**)&hr,   g_hr);
    cudaGetSymbolAddress((void**)&csum, g_csum);
    cudaGetSymbolAddress((void**)&csq,  g_csq);
    cudaGetSymbolAddress((void**)&SA1,  g_SA1);
    cudaGetSymbolAddress((void**)&SA2,  g_SA2);
    cudaGetSymbolAddress((void**)&SA3,  g_SA3);
    cudaGetSymbolAddress((void**)&WbC,  g_WbC);
    cudaGetSymbolAddress((void**)&Wb,   g_Wb);
    cudaGetSymbolAddress((void**)&Wb2,  g_Wb2);
    cudaGetSymbolAddress((void**)&hrA,  g_hrA);

    cudaMemcpyAsync(XR, emb, (size_t)N_TOT * EMB * sizeof(float),
                    cudaMemcpyDeviceToDevice);

    const dim3 gWC(4, (N_TOT + BM - 1) / BM);       // fused sup GEMM: N=512
    const dim3 gWe(2, (N_ENTS + BM - 1) / BM);      // lin GEMM: N=256
    const dim3 gS((N_ENTS + BN - 1) / BN, (BATCH + BM - 1) / BM);
    const int BLK_TOT = (N_TOT * 64 + 255) / 256;
    const int BLK_BOTH = (N_TOT * 64 + N_ENTS * 64 + 255) / 256;
    const int BLK_HAM = (EMB * EMB + 255) / 256;

    // fork s_mem FROM the captured stream, then layer-0 memsets on it
    cudaEventRecord(evF, 0);
    cudaStreamWaitEvent(s_mem, evF, 0);
    cudaMemsetAsync(agg,  0, (size_t)N_TOT * EMB * sizeof(float), s_mem);
    cudaMemsetAsync(aggX, 0, (size_t)N_ENTS * EMB * sizeof(float), s_mem);
    cudaMemsetAsync(csum, 0, 2 * EMB * sizeof(float), s_mem);
    cudaMemsetAsync(csq,  0, 2 * EMB * sizeof(float), s_mem);
    cudaEventRecord(evMd[0], s_mem);

    // prologue — gemm at launch #4 for ncu
    split_hl<<<BLK_TOT, 256>>>(XR, SA1, N_TOT * 64);                             // #1
    cudaEventRecord(evA[0], 0);   // XR + SA1 ready for score 0
    build_ham_split<<<BLK_HAM, 256>>>(gcn2_w, WbC, 0);                           // #2
    build_ham_split<<<BLK_HAM, 256>>>(gcn1_w, WbC, 256);                         // #3

    for (int l = 0; l < 2; l++) {
        // ---- main: fused sup GEMM (both branches, N=512) ----
        if (l > 0) {
            build_ham_split<<<BLK_HAM, 256>>>(gcn2_w + (size_t)l * 64 * EMB, WbC, 0);
            build_ham_split<<<BLK_HAM, 256>>>(gcn1_w + (size_t)l * 64 * EMB, WbC, 256);
        }
        gemm_bf16<EPI_STORE, false><<<gWC, 256, SM_GEMM>>>(SA1, WbC, nullptr, nullptr,
                                                           supC, N_TOT, 512);   // #4 at l=0

        // ---- side: score(l) overlapped with the spmm/bn chain ----
        cudaStreamWaitEvent(s_side, evA[l], 0);
        vecvec<<<BATCH, 64, 0, s_side>>>(XR, XR + (size_t)N_ENTS * EMB, e1, ri, hr);
        cudaEventRecord(evV[l], s_side);              // XR no longer read by side
        bn_batch<<<1, 1024, 0, s_side>>>(hr, bsg + l * EMB, bsb + l * EMB);
        split_hl<<<(BATCH * 64 + 255) / 256, 256, 0, s_side>>>(hr, hrA, BATCH * 64);
        gemm_bf16<EPI_SIG, false><<<gS, 256, SM_GEMM, s_side>>>(
            hrA, SA1, nullptr, nullptr, out + (size_t)l * BATCH * N_ENTS, BATCH, N_ENTS);
        cudaEventRecord(evS[l], s_side);              // SA1 no longer read by side

        // ---- main: merged segment-sum + stats ----
        cudaStreamWaitEvent(0, evMd[l], 0);           // memsets complete
        spmm2<<<(2 * N_EDGES + 3) / 4, 256>>>(ar_rows, ar_cols, ar_vals, supC, agg,
                                              a_rows, a_cols, a_vals, supC + 256, aggX);
        colstats2<<<NB_XR + NB_X, EMB>>>(agg, aggX);
        bn_final2<<<1, 2 * EMB>>>(g2_gam + l * EMB, g2_bet + l * EMB,
                                  g1_gam + l * EMB, g1_bet + l * EMB);
        cudaStreamWaitEvent(0, evV[l], 0);            // side done reading XR
        bn_tanh_split2<<<BLK_BOTH, 256>>>(agg, XR, SA2, aggX, SA3,
                                          N_TOT * 64, N_ENTS * 64);
        if (l == 0) {
            // memsets for layer 1 on s_mem (agg fully consumed by bn_tanh_split2)
            cudaEventRecord(evM[1], 0);
            cudaStreamWaitEvent(s_mem, evM[1], 0);
            cudaMemsetAsync(agg,  0, (size_t)N_TOT * EMB * sizeof(float), s_mem);
            cudaMemsetAsync(aggX, 0, (size_t)N_ENTS * EMB * sizeof(float), s_mem);
            cudaMemsetAsync(csum, 0, 2 * EMB * sizeof(float), s_mem);
            cudaMemsetAsync(csq,  0, 2 * EMB * sizeof(float), s_mem);
            cudaEventRecord(evMd[1], s_mem);
        }

        // ---- main: fused lin: X_new = Xef @ H1^T + Xrf @ H2^T (24-chunk dual) ----
        build_lin_split<<<EMB, EMB>>>(lin + (size_t)l * 128 * EMB, Wb, Wb2);
        gemm_bf16<EPI_STORE, true><<<gWe, 256, SM_GEMM>>>(SA3, Wb, SA2, Wb2,
                                                          XR, N_ENTS, EMB);

        cudaStreamWaitEvent(0, evS[l], 0);            // side done reading SA1 (joins side)
        split_hl<<<BLK_TOT, 256>>>(XR, SA1, N_TOT * 64);
        if (l == 0) cudaEventRecord(evA[1], 0);       // ready for score 1
    }

    // final score on main (terminal)
    vecvec<<<BATCH, 64>>>(XR, XR + (size_t)N_ENTS * EMB, e1, ri, hr);
    bn_batch<<<1, 1024>>>(hr, bsg + 2 * EMB, bsb + 2 * EMB);
    split_hl<<<(BATCH * 64 + 255) / 256, 256>>>(hr, hrA, BATCH * 64);
    gemm_bf16<EPI_SIG, false><<<gS, 256, SM_GEMM>>>(
        hrA, SA1, nullptr, nullptr, out + (size_t)2 * BATCH * N_ENTS, BATCH, N_ENTS);
}

// round 14
// speedup vs baseline: 1.0875x; 1.0079x over previous
#include <cuda_runtime.h>
#include <cuda_bf16.h>
#include <stdint.h>

#define N_ENTS 50000
#define N_RELS 500
#define N_TOT  50500
#define EMB    256
#define N_EDGES 400000
#define BATCH  512
#define BN_EPS 1e-5f
#define KS2    512   // h|l storage width (bf16x3 streams 768 via chunk tables)

// ---------------- scratch (__device__ globals, no allocations) ----------------
__device__ float g_XR[(size_t)N_TOT * EMB];
__device__ float g_sup1[(size_t)N_TOT * EMB];       // XR-branch support (stride 256)
__device__ float g_sup2[(size_t)N_ENTS * EMB];      // X-branch support (stride 256)
__device__ float g_agg[(size_t)N_TOT * EMB];        // XR-branch segment sum
__device__ float g_aggX[(size_t)N_ENTS * EMB];      // X-branch segment sum
__device__ float g_hr[(size_t)BATCH * EMB];
__device__ float g_csum[2 * EMB];
__device__ float g_csq[2 * EMB];
__device__ float g_scale[2 * EMB];
__device__ float g_shift[2 * EMB];

// h|l split buffers: [n, 512] bf16, cols 0-255 = hi, 256-511 = lo
__device__ __nv_bfloat16 g_SA1[(size_t)N_TOT * KS2];     // split of XR
__device__ __nv_bfloat16 g_SA2[(size_t)N_TOT * KS2];     // split of XRrf
__device__ __nv_bfloat16 g_SA3[(size_t)N_ENTS * KS2];    // split of Xef
__device__ __nv_bfloat16 g_WbC[512 * KS2];               // gcn weights: rows 0-255 g2, 256-511 g1
__device__ __nv_bfloat16 g_Wb[EMB * KS2];                // lin weights H1
__device__ __nv_bfloat16 g_Wb2[EMB * KS2];               // lin weights H2
__device__ __nv_bfloat16 g_hrA[(size_t)BATCH * KS2];     // split hr

// quaternion block tables
__constant__ int   c_comp[4][4] = {{0,1,2,3},{1,0,3,2},{2,3,0,1},{3,2,1,0}};
__constant__ float c_sign[4][4] = {{ 1.f, 1.f, 1.f, 1.f},
                                   {-1.f, 1.f, 1.f,-1.f},
                                   {-1.f,-1.f, 1.f, 1.f},
                                   {-1.f, 1.f,-1.f, 1.f}};

// bf16x3 chunk schedule (64-half chunks): AhBh x4, AlBh x4, AhBl x4
__constant__ int c_ka[12] = {0,64,128,192, 256,320,384,448, 0,64,128,192};
__constant__ int c_kb[12] = {0,64,128,192, 0,64,128,192, 256,320,384,448};

// ---------------- helpers ----------------
static __device__ __forceinline__ void split1(float x, __nv_bfloat16& h, __nv_bfloat16& l) {
    h = __float2bfloat16(x);
    l = __float2bfloat16(x - __bfloat162float(h));
}
static __device__ __forceinline__ uint32_t pack2(__nv_bfloat16 a, __nv_bfloat16 b) {
    return ((uint32_t)__bfloat16_as_ushort(b) << 16) | __bfloat16_as_ushort(a);
}
static __device__ __forceinline__ uint2 pack4(__nv_bfloat16 a, __nv_bfloat16 b,
                                              __nv_bfloat16 c, __nv_bfloat16 d) {
    uint2 u;
    u.x = pack2(a, b);
    u.y = pack2(c, d);
    return u;
}

// ---------------- fused hamilton build + h|l split ----------------
__global__ void build_ham_split(const float* __restrict__ W, __nv_bfloat16* __restrict__ out,
                                int off) {
    int idx = blockIdx.x * blockDim.x + threadIdx.x;
    if (idx >= EMB * EMB) return;
    int c = idx >> 8, k = idx & 255;
    int a = k >> 6, u = k & 63, b = c >> 6, v = c & 63;
    float val = c_sign[a][b] * W[u * EMB + c_comp[a][b] * 64 + v];
    __nv_bfloat16 h, l;
    split1(val, h, l);
    size_t base = (size_t)(off + c) * KS2;
    out[base + k] = h;
    out[base + 256 + k] = l;
}

__global__ void build_lin_split(const float* __restrict__ W, __nv_bfloat16* __restrict__ o1,
                                __nv_bfloat16* __restrict__ o2) {
    int c = blockIdx.x, j = threadIdx.x;
    int q = j >> 6, s = j & 63;
    int b = c >> 6, v = c & 63;
    int pe = 128 * q + s;
    int pr = pe + 64;
    int a1 = pe >> 7, u1 = pe & 127;
    int a2 = pr >> 7, u2 = pr & 127;
    float v1 = c_sign[a1][b] * W[u1 * EMB + c_comp[a1][b] * 64 + v];
    float v2 = c_sign[a2][b] * W[u2 * EMB + c_comp[a2][b] * 64 + v];
    __nv_bfloat16 h, l;
    size_t base = (size_t)c * KS2;
    split1(v1, h, l); o1[base + j] = h; o1[base + 256 + j] = l;
    split1(v2, h, l); o2[base + j] = h; o2[base + 256 + j] = l;
}

// ---------------- h|l split conversion ----------------
__global__ void split_hl(const float* __restrict__ in, __nv_bfloat16* __restrict__ out,
                         int n64) {
    int i = blockIdx.x * blockDim.x + threadIdx.x;
    if (i >= n64) return;
    int r = i >> 6, c4 = (i & 63) << 2;
    float4 x = *(const float4*)(in + (size_t)r * EMB + c4);
    __nv_bfloat16 h[4], l[4];
    split1(x.x, h[0], l[0]); split1(x.y, h[1], l[1]);
    split1(x.z, h[2], l[2]); split1(x.w, h[3], l[3]);
    size_t b = (size_t)r * KS2 + c4;
    *(uint2*)(out + b) = pack4(h[0], h[1], h[2], h[3]);
    *(uint2*)(out + b + 256) = pack4(l[0], l[1], l[2], l[3]);
}

// merged bn+tanh+split for BOTH branches in one launch.
// part 1 (i < n1_64): agg -> SA2, scale offset 0, R-rows written to XRout.
// part 2:             aggX -> SA3, scale offset 256.
__global__ void bn_tanh_split2(const float* __restrict__ in1, float* __restrict__ XRout,
                               __nv_bfloat16* __restrict__ out1,
                               const float* __restrict__ in2,
                               __nv_bfloat16* __restrict__ out2,
                               int n1_64, int n2_64) {
    int i = blockIdx.x * blockDim.x + threadIdx.x;
    const float* in;
    __nv_bfloat16* out;
    int so;
    bool wrr;
    if (i < n1_64) { in = in1; out = out1; so = 0; wrr = true; }
    else { i -= n1_64; if (i >= n2_64) return; in = in2; out = out2; so = 256; wrr = false; }
    int r = i >> 6, c4 = (i & 63) << 2;
    float4 x = *(const float4*)(in + (size_t)r * EMB + c4);
    float y[4];
    float* xs = &x.x;
#pragma unroll
    for (int j = 0; j < 4; j++) {
        float z = xs[j] * g_scale[so + c4 + j] + g_shift[so + c4 + j];
        float e = __expf(-2.f * fabsf(z));
        float t = (1.f - e) / (1.f + e);
        y[j] = copysignf(t, z);
    }
    if (wrr && r >= N_ENTS)
        *(float4*)(XRout + (size_t)r * EMB + c4) = make_float4(y[0], y[1], y[2], y[3]);
    __nv_bfloat16 h[4], l[4];
#pragma unroll
    for (int j = 0; j < 4; j++) split1(y[j], h[j], l[j]);
    size_t b = (size_t)r * KS2 + c4;
    *(uint2*)(out + b) = pack4(h[0], h[1], h[2], h[3]);
    *(uint2*)(out + b + 256) = pack4(l[0], l[1], l[2], l[3]);
}

// ====== bf16 HMMA GEMM: 128x128 tile, 64x32 warps, 3-stage, 2 CTA/SM ======
// DUAL: 24 chunks — 0-11 from (A,B), 12-23 from (A+dA, B+dB); accumulates both products.
// EPI_SPLIT: also writes the h|l bf16 split of C into Csplit (row stride KS2).
enum { EPI_STORE = 0, EPI_SIG = 2, EPI_SPLIT = 3 };

#define BM 128
#define BN 128
#define STAGE_SZ 32768            // A 16KB + B 16KB
#define SM_GEMM (3 * STAGE_SZ)    // 98304

static __device__ __forceinline__ uint32_t cvtas(const void* p) {
    uint32_t a;
    asm("{ .reg .u64 t; cvta.to.shared.u64 t, %1; cvt.u32.u64 %0, t; }" : "=r"(a) : "l"(p));
    return a;
}
static __device__ __forceinline__ uint32_t swz(uint32_t o) { return o ^ ((o >> 3) & 0x70); }
static __device__ __forceinline__ void cp16(uint32_t d, const void* g, int sz) {
    asm volatile("cp.async.cg.shared.global [%0], [%1], 16, %2;" :: "r"(d), "l"(g), "r"(sz));
}
static __device__ __forceinline__ void ldsm4(uint32_t& d0, uint32_t& d1, uint32_t& d2,
                                             uint32_t& d3, uint32_t a) {
    asm volatile("ldmatrix.sync.aligned.m8n8.x4.shared.b16 {%0,%1,%2,%3}, [%4];"
                 : "=r"(d0), "=r"(d1), "=r"(d2), "=r"(d3) : "r"(a));
}
static __device__ __forceinline__ void mma16816(float* c, uint32_t a0, uint32_t a1,
                                                uint32_t a2, uint32_t a3,
                                                uint32_t b0, uint32_t b1) {
    asm volatile("mma.sync.aligned.m16n8k16.row.col.f32.bf16.bf16.f32 "
                 "{%0,%1,%2,%3}, {%4,%5,%6,%7}, {%8,%9}, {%0,%1,%2,%3};"
                 : "+f"(c[0]), "+f"(c[1]), "+f"(c[2]), "+f"(c[3])
                 : "r"(a0), "r"(a1), "r"(a2), "r"(a3), "r"(b0), "r"(b1));
}

template <int EPI, bool DUAL>
__global__ void __launch_bounds__(256, 2)
gemm_bf16(const __nv_bfloat16* __restrict__ A, const __nv_bfloat16* __restrict__ B,
          const __nv_bfloat16* __restrict__ A2, const __nv_bfloat16* __restrict__ B2,
          float* __restrict__ C, __nv_bfloat16* __restrict__ Csplit, int M, int N) {
    extern __shared__ char smem[];
    const uint32_t sb = cvtas(smem);
    const uint32_t stB[3] = { sb, sb + STAGE_SZ, sb + 2 * STAGE_SZ };
    const int NKC = DUAL ? 24 : 12;

    const int tid = threadIdx.x;
    const int lane = tid & 31, wid = tid >> 5;
    const int wm = wid >> 2, wn = wid & 3;
    const int m0 = blockIdx.y * BM, n0 = blockIdx.x * BN;

    const int r0 = tid >> 2;
    const int c2 = (tid & 3) * 2;
    uint32_t soff[2][2];
#pragma unroll
    for (int r = 0; r < 2; r++)
#pragma unroll
        for (int q = 0; q < 2; q++)
            soff[r][q] = swz((uint32_t)(r0 + r * 64) * 128 + (uint32_t)(c2 + q) * 16);

    int szA[2], szB[2];
    const __nv_bfloat16 *Ag[2], *Bg[2];
#pragma unroll
    for (int r = 0; r < 2; r++) {
        long mr = m0 + r0 + r * 64, nr = n0 + r0 + r * 64;
        szA[r] = mr < M ? 16 : 0;
        szB[r] = nr < N ? 16 : 0;
        Ag[r] = A + (size_t)(mr < M ? mr : M - 1) * KS2 + c2 * 8;
        Bg[r] = B + (size_t)(nr < N ? nr : N - 1) * KS2 + c2 * 8;
    }
    const ptrdiff_t dA = DUAL ? (A2 - A) : 0;
    const ptrdiff_t dB = DUAL ? (B2 - B) : 0;

    float acc[4][4][4];
#pragma unroll
    for (int i = 0; i < 4; i++)
#pragma unroll
        for (int j = 0; j < 4; j++)
#pragma unroll
            for (int q = 0; q < 4; q++) acc[i][j][q] = 0.f;

    auto issue = [&](uint32_t stBase, int kc) {
        const bool p2 = DUAL && (kc >= 12);
        const int kcm = p2 ? kc - 12 : kc;
        const int ka = c_ka[kcm], kb = c_kb[kcm];
        const ptrdiff_t oa = p2 ? dA : 0, ob = p2 ? dB : 0;
        const uint32_t aB = stBase, bB_ = stBase + 16384;
#pragma unroll
        for (int q = 0; q < 2; q++)
#pragma unroll
            for (int r = 0; r < 2; r++) {
                cp16(aB + soff[r][q], Ag[r] + oa + ka + q * 8, szA[r]);
                cp16(bB_ + soff[r][q], Bg[r] + ob + kb + q * 8, szB[r]);
            }
        asm volatile("cp.async.commit_group;");
    };

    const uint32_t aRow = (uint32_t)(wm * 64 + (lane & 15));
    const uint32_t aChk = (uint32_t)(lane >> 4);
    const uint32_t bRow0 = (uint32_t)(wn * 32 + (lane & 7) + ((lane >> 4) & 1) * 8);
    const uint32_t bChk = (uint32_t)((lane >> 3) & 1);

    auto compute = [&](uint32_t stBase) {
        const uint32_t aB = stBase, bB_ = stBase + 16384;
#pragma unroll
        for (int ks = 0; ks < 4; ks++) {
            uint32_t a[4][4];
#pragma unroll
            for (int mi = 0; mi < 4; mi++) {
                uint32_t o = (aRow + mi * 16) * 128 + (2 * ks + aChk) * 16;
                ldsm4(a[mi][0], a[mi][1], a[mi][2], a[mi][3], aB + swz(o));
            }
            uint32_t bf[4][2];
#pragma unroll
            for (int j = 0; j < 2; j++) {
                uint32_t t0, t1, t2, t3;
                uint32_t o = (bRow0 + j * 16) * 128 + (2 * ks + bChk) * 16;
                ldsm4(t0, t1, t2, t3, bB_ + swz(o));
                bf[2 * j][0] = t0;     bf[2 * j][1] = t1;
                bf[2 * j + 1][0] = t2; bf[2 * j + 1][1] = t3;
            }
#pragma unroll
            for (int mi = 0; mi < 4; mi++)
#pragma unroll
                for (int nj = 0; nj < 4; nj++)
                    mma16816(acc[mi][nj], a[mi][0], a[mi][1], a[mi][2], a[mi][3],
                             bf[nj][0], bf[nj][1]);
        }
    };

    issue(stB[0], 0);
    issue(stB[1], 1);
    auto step = [&](int kc, int st) {
        asm volatile("cp.async.wait_group 1;");
        __syncthreads();
        compute(stB[st]);
        if (kc + 2 < NKC) issue(stB[(st + 2) % 3], kc + 2);
        else asm volatile("cp.async.commit_group;");
    };
#pragma unroll 1
    for (int kc = 0; kc < NKC; kc += 3) {
        step(kc, 0); step(kc + 1, 1); step(kc + 2, 2);
    }

    // epilogue
#pragma unroll
    for (int mi = 0; mi < 4; mi++) {
        int row = m0 + wm * 64 + mi * 16 + (lane >> 2);
#pragma unroll
        for (int nj = 0; nj < 4; nj++) {
            int col = n0 + wn * 32 + nj * 8 + (lane & 3) * 2;
            float* cf = acc[mi][nj];
#pragma unroll
            for (int h = 0; h < 2; h++) {
                int r = row + h * 8;
                if (r >= M) continue;
                float* p = C + (size_t)r * N + col;
                float v0 = cf[h * 2 + 0], v1 = cf[h * 2 + 1];
                if (EPI == EPI_SIG) {
                    v0 = 1.f / (1.f + __expf(-v0));
                    v1 = 1.f / (1.f + __expf(-v1));
                }
                if (col < N) p[0] = v0;
                if (col + 1 < N) p[1] = v1;
                if (EPI == EPI_SPLIT && col + 1 < N) {
                    __nv_bfloat16 h0, l0, h1, l1;
                    split1(v0, h0, l0);
                    split1(v1, h1, l1);
                    *(uint32_t*)(Csplit + (size_t)r * KS2 + col) = pack2(h0, h1);
                    *(uint32_t*)(Csplit + (size_t)r * KS2 + 256 + col) = pack2(l0, l1);
                }
            }
        }
    }
}

// ---------------- SpMM single graph (sup row stride 256) ----------------
__global__ void spmm(const int* __restrict__ R, const int* __restrict__ C,
                     const float* __restrict__ V, const float* __restrict__ S,
                     float* __restrict__ A) {
    int e = blockIdx.x * 4 + (threadIdx.x >> 6);
    if (e >= N_EDGES) return;
    int t = threadIdx.x & 63;
    int r = R[e], c = C[e];
    float v = V[e];
    float4 s = *(const float4*)(S + (size_t)c * EMB + t * 4);
    float4 a = make_float4(v * s.x, v * s.y, v * s.z, v * s.w);
    atomicAdd((float4*)(A + (size_t)r * EMB + t * 4), a);
}

// ---------------- merged node batchnorm stats (both branches) ----------------
#define NB_XR 198   // ceil(N_TOT/256)
#define NB_X  196   // ceil(N_ENTS/256)
__global__ void colstats2(const float* __restrict__ aggXR, const float* __restrict__ aggX) {
    int c = threadIdx.x;
    int b = blockIdx.x;
    const float* X;
    int r0, r1, off;
    if (b < NB_XR) { X = aggXR; r0 = b * 256; r1 = min(r0 + 256, N_TOT); off = 0; }
    else { X = aggX; r0 = (b - NB_XR) * 256; r1 = min(r0 + 256, N_ENTS); off = 256; }
    float s = 0.f, s2 = 0.f;
    for (int r = r0; r < r1; r++) {
        float v = X[(size_t)r * EMB + c];
        s += v; s2 += v * v;
    }
    atomicAdd(&g_csum[off + c], s);
    atomicAdd(&g_csq[off + c], s2);
}

__global__ void bn_final2(const float* __restrict__ g2g, const float* __restrict__ g2b,
                          const float* __restrict__ g1g, const float* __restrict__ g1b) {
    int c = threadIdx.x;   // 0..511
    float inv_n = c < 256 ? (1.f / N_TOT) : (1.f / N_ENTS);
    float gam = c < 256 ? g2g[c] : g1g[c - 256];
    float bet = c < 256 ? g2b[c] : g1b[c - 256];
    float m = g_csum[c] * inv_n;
    float var = g_csq[c] * inv_n - m * m;
    float sc = rsqrtf(var + BN_EPS) * gam;
    g_scale[c] = sc;
    g_shift[c] = bet - m * sc;
}

// ---------------- score head ----------------
__global__ void vecvec(const float* __restrict__ X, const float* __restrict__ R,
                       const int* __restrict__ e1, const int* __restrict__ ri,
                       float* __restrict__ hr) {
    int b = blockIdx.x;
    int s = threadIdx.x;
    const float* h = X + (size_t)e1[b] * EMB;
    const float* p = R + (size_t)ri[b] * EMB;
    float pr = p[s], pi = p[64 + s], pj = p[128 + s], pk = p[192 + s];
    float inv = rsqrtf(pr * pr + pi * pi + pj * pj + pk * pk);
    pr *= inv; pi *= inv; pj *= inv; pk *= inv;
    float qr = h[s], qi = h[64 + s], qj = h[128 + s], qk = h[192 + s];
    float* o = hr + (size_t)b * EMB;
    o[s]       = qr * pr - qi * pi - qj * pj - qk * pk;
    o[64 + s]  = qi * pr + qr * pi - qk * pj + qj * pk;
    o[128 + s] = qj * pr + qk * pi + qr * pj - qi * pk;
    o[192 + s] = qk * pr - qj * pi + qi * pj + qr * pk;
}

__global__ void __launch_bounds__(1024)
bn_batch(float* __restrict__ hr, const float* __restrict__ gamma,
         const float* __restrict__ beta) {
    __shared__ float ss[4][EMB], sq[4][EMB], sc[EMB], sh[EMB];
    int c = threadIdx.x & 255, g = threadIdx.x >> 8;
    float s = 0.f, s2 = 0.f;
    for (int b = g * 128; b < g * 128 + 128; b++) {
        float v = hr[(size_t)b * EMB + c];
        s += v; s2 += v * v;
    }
    ss[g][c] = s; sq[g][c] = s2;
    __syncthreads();
    if (g == 0) {
        float S = ss[0][c] + ss[1][c] + ss[2][c] + ss[3][c];
        float Q = sq[0][c] + sq[1][c] + sq[2][c] + sq[3][c];
        float m = S * (1.f / BATCH);
        float var = Q * (1.f / BATCH) - m * m;
        float scale = rsqrtf(var + BN_EPS) * gamma[c];
        sc[c] = scale; sh[c] = beta[c] - m * scale;
    }
    __syncthreads();
    float scale = sc[c], shift = sh[c];
    for (int b = g * 128; b < g * 128 + 128; b++)
        hr[(size_t)b * EMB + c] = hr[(size_t)b * EMB + c] * scale + shift;
}

// ---------------- host orchestration ----------------
extern "C" void kernel_launch(void* const* d_in, const int* in_sizes, int n_in,
                              void* d_out, int out_size) {
    const int*   e1      = (const int*)d_in[0];
    const int*   ri      = (const int*)d_in[1];
    const float* emb     = (const float*)d_in[2];
    const float* gcn1_w  = (const float*)d_in[3];
    const float* gcn2_w  = (const float*)d_in[4];
    const float* g1_gam  = (const float*)d_in[5];
    const float* g1_bet  = (const float*)d_in[6];
    const float* g2_gam  = (const float*)d_in[7];
    const float* g2_bet  = (const float*)d_in[8];
    const float* lin     = (const float*)d_in[9];
    const float* bsg     = (const float*)d_in[10];
    const float* bsb     = (const float*)d_in[11];
    const int*   a_rows  = (const int*)d_in[12];
    const int*   a_cols  = (const int*)d_in[13];
    const float* a_vals  = (const float*)d_in[14];
    const int*   ar_rows = (const int*)d_in[15];
    const int*   ar_cols = (const int*)d_in[16];
    const float* ar_vals = (const float*)d_in[17];
    float* out = (float*)d_out;

    cudaFuncSetAttribute(gemm_bf16<EPI_STORE, false>, cudaFuncAttributeMaxDynamicSharedMemorySize, SM_GEMM);
    cudaFuncSetAttribute(gemm_bf16<EPI_SPLIT, true>,  cudaFuncAttributeMaxDynamicSharedMemorySize, SM_GEMM);
    cudaFuncSetAttribute(gemm_bf16<EPI_SIG, false>,   cudaFuncAttributeMaxDynamicSharedMemorySize, SM_GEMM);

    static cudaStream_t s_side = nullptr, s_mem = nullptr, s_aux = nullptr;
    static cudaEvent_t evF, evA[2], evV[2], evS[2], evM[2], evMd[2], evG1[2], evG2[2];
    if (!s_side) {
        cudaStreamCreateWithFlags(&s_side, cudaStreamNonBlocking);
        cudaStreamCreateWithFlags(&s_mem,  cudaStreamNonBlocking);
        cudaStreamCreateWithFlags(&s_aux,  cudaStreamNonBlocking);
        cudaEventCreateWithFlags(&evF, cudaEventDisableTiming);
        for (int i = 0; i < 2; i++) {
            cudaEventCreateWithFlags(&evA[i],  cudaEventDisableTiming);
            cudaEventCreateWithFlags(&evV[i],  cudaEventDisableTiming);
            cudaEventCreateWithFlags(&evS[i],  cudaEventDisableTiming);
            cudaEventCreateWithFlags(&evM[i],  cudaEventDisableTiming);
            cudaEventCreateWithFlags(&evMd[i], cudaEventDisableTiming);
            cudaEventCreateWithFlags(&evG1[i], cudaEventDisableTiming);
            cudaEventCreateWithFlags(&evG2[i], cudaEventDisableTiming);
        }
    }

    float *XR, *sup1, *sup2, *agg, *aggX, *hr, *csum, *csq;
    __nv_bfloat16 *SA1, *SA2, *SA3, *WbC, *Wb, *Wb2, *hrA;
    cudaGetSymbolAddress((void**)&XR,   g_XR);
    cudaGetSymbolAddress((void**)&sup1, g_sup1);
    cudaGetSymbolAddress((void**)&sup2, g_sup2);
    cudaGetSymbolAddress((void**)&agg,  g_agg);
    cudaGetSymbolAddress((void**)&aggX, g_aggX);
    cudaGetSymbolAddress((void**)&hr,   g_hr);
    cudaGetSymbolAddress((void**)&csum, g_csum);
    cudaGetSymbolAddress((void**)&csq,  g_csq);
    cudaGetSymbolAddress((void**)&SA1,  g_SA1);
    cudaGetSymbolAddress((void**)&SA2,  g_SA2);
    cudaGetSymbolAddress((void**)&SA3,  g_SA3);
    cudaGetSymbolAddress((void**)&WbC,  g_WbC);
    cudaGetSymbolAddress((void**)&Wb,   g_Wb);
    cudaGetSymbolAddress((void**)&Wb2,  g_Wb2);
    cudaGetSymbolAddress((void**)&hrA,  g_hrA);

    cudaMemcpyAsync(XR, emb, (size_t)N_TOT * EMB * sizeof(float),
                    cudaMemcpyDeviceToDevice);

    const dim3 gWt(2, (N_TOT + BM - 1) / BM);       // N_TOT x 256 GEMM
    const dim3 gWe(2, (N_ENTS + BM - 1) / BM);      // N_ENTS x 256 GEMM
    const dim3 gS((N_ENTS + BN - 1) / BN, (BATCH + BM - 1) / BM);
    const int BLK_TOT = (N_TOT * 64 + 255) / 256;
    const int BLK_BOTH = (N_TOT * 64 + N_ENTS * 64 + 255) / 256;
    const int BLK_HAM = (EMB * EMB + 255) / 256;
    const int G_SPMM = (N_EDGES + 3) / 4;

    // fork s_mem FROM the captured stream, then layer-0 memsets on it
    cudaEventRecord(evF, 0);
    cudaStreamWaitEvent(s_mem, evF, 0);
    cudaMemsetAsync(agg,  0, (size_t)N_TOT * EMB * sizeof(float), s_mem);
    cudaMemsetAsync(aggX, 0, (size_t)N_ENTS * EMB * sizeof(float), s_mem);
    cudaMemsetAsync(csum, 0, 2 * EMB * sizeof(float), s_mem);
    cudaMemsetAsync(csq,  0, 2 * EMB * sizeof(float), s_mem);
    cudaEventRecord(evMd[0], s_mem);

    // prologue — gemm at launch #4 for ncu
    split_hl<<<BLK_TOT, 256>>>(XR, SA1, N_TOT * 64);                             // #1
    cudaEventRecord(evA[0], 0);   // XR + SA1 ready for score 0
    build_ham_split<<<BLK_HAM, 256>>>(gcn2_w, WbC, 0);                           // #2
    build_ham_split<<<BLK_HAM, 256>>>(gcn1_w, WbC, 256);                         // #3

    for (int l = 0; l < 2; l++) {
        if (l > 0) {
            build_ham_split<<<BLK_HAM, 256>>>(gcn2_w + (size_t)l * 64 * EMB, WbC, 0);
            build_ham_split<<<BLK_HAM, 256>>>(gcn1_w + (size_t)l * 64 * EMB, WbC, 256);
        }
        // ---- main: XR-branch sup GEMM ----
        gemm_bf16<EPI_STORE, false><<<gWt, 256, SM_GEMM>>>(
            SA1, WbC, nullptr, nullptr, sup1, nullptr, N_TOT, EMB);   // #4 at l=0
        cudaEventRecord(evG1[l], 0);

        // ---- aux: X-branch sup GEMM (overlaps spmm1 below) ----
        cudaStreamWaitEvent(s_aux, evG1[l], 0);
        gemm_bf16<EPI_STORE, false><<<gWe, 256, SM_GEMM, s_aux>>>(
            SA1, WbC + 256 * KS2, nullptr, nullptr, sup2, nullptr, N_ENTS, EMB);
        cudaEventRecord(evG2[l], s_aux);

        // ---- side: score(l) overlapped with the spmm/bn chain ----
        cudaStreamWaitEvent(s_side, evA[l], 0);
        vecvec<<<BATCH, 64, 0, s_side>>>(XR, XR + (size_t)N_ENTS * EMB, e1, ri, hr);
        cudaEventRecord(evV[l], s_side);              // XR no longer read by side
        bn_batch<<<1, 1024, 0, s_side>>>(hr, bsg + l * EMB, bsb + l * EMB);
        split_hl<<<(BATCH * 64 + 255) / 256, 256, 0, s_side>>>(hr, hrA, BATCH * 64);
        gemm_bf16<EPI_SIG, false><<<gS, 256, SM_GEMM, s_side>>>(
            hrA, SA1, nullptr, nullptr, out + (size_t)l * BATCH * N_ENTS, nullptr,
            BATCH, N_ENTS);
        cudaEventRecord(evS[l], s_side);              // SA1 no longer read by side

        // ---- main: segment-sums (spmm1 overlaps aux gemm2) ----
        cudaStreamWaitEvent(0, evMd[l], 0);           // memsets complete
        spmm<<<G_SPMM, 256>>>(ar_rows, ar_cols, ar_vals, sup1, agg);
        cudaStreamWaitEvent(0, evG2[l], 0);           // sup2 ready
        spmm<<<G_SPMM, 256>>>(a_rows, a_cols, a_vals, sup2, aggX);
        colstats2<<<NB_XR + NB_X, EMB>>>(agg, aggX);
        bn_final2<<<1, 2 * EMB>>>(g2_gam + l * EMB, g2_bet + l * EMB,
                                  g1_gam + l * EMB, g1_bet + l * EMB);
        cudaStreamWaitEvent(0, evV[l], 0);            // side done reading XR
        bn_tanh_split2<<<BLK_BOTH, 256>>>(agg, XR, SA2, aggX, SA3,
                                          N_TOT * 64, N_ENTS * 64);
        if (l == 0) {
            cudaEventRecord(evM[1], 0);
            cudaStreamWaitEvent(s_mem, evM[1], 0);
            cudaMemsetAsync(agg,  0, (size_t)N_TOT * EMB * sizeof(float), s_mem);
            cudaMemsetAsync(aggX, 0, (size_t)N_ENTS * EMB * sizeof(float), s_mem);
            cudaMemsetAsync(csum, 0, 2 * EMB * sizeof(float), s_mem);
            cudaMemsetAsync(csq,  0, 2 * EMB * sizeof(float), s_mem);
            cudaEventRecord(evMd[1], s_mem);
        }

        // ---- main: fused lin GEMM writing XR + SA1 split (waits side's SA1 reads) ----
        build_lin_split<<<EMB, EMB>>>(lin + (size_t)l * 128 * EMB, Wb, Wb2);
        cudaStreamWaitEvent(0, evS[l], 0);            // side score done reading SA1
        gemm_bf16<EPI_SPLIT, true><<<gWe, 256, SM_GEMM>>>(
            SA3, Wb, SA2, Wb2, XR, SA1, N_ENTS, EMB);
        // SA1 R-rows = split(XRrf R-rows) = SA2 R-rows
        cudaMemcpyAsync(SA1 + (size_t)N_ENTS * KS2, SA2 + (size_t)N_ENTS * KS2,
                        (size_t)N_RELS * KS2 * sizeof(__nv_bfloat16),
                        cudaMemcpyDeviceToDevice);
        if (l == 0) cudaEventRecord(evA[1], 0);       // XR + SA1 ready for score 1
    }

    // final score on main (terminal)
    vecvec<<<BATCH, 64>>>(XR, XR + (size_t)N_ENTS * EMB, e1, ri, hr);
    bn_batch<<<1, 1024>>>(hr, bsg + 2 * EMB, bsb + 2 * EMB);
    split_hl<<<(BATCH * 64 + 255) / 256, 256>>>(hr, hrA, BATCH * 64);
    gemm_bf16<EPI_SIG, false><<<gS, 256, SM_GEMM>>>(
        hrA, SA1, nullptr, nullptr, out + (size_t)2 * BATCH * N_ENTS, nullptr,
        BATCH, N_ENTS);
}